// round 3
// baseline (speedup 1.0000x reference)
#include <cuda_runtime.h>
#include <cuda_fp16.h>

#define N_NODES 50000
#define N_EDGES 800000
#define D_FEAT  128

// ---- device-global scratch (no runtime allocation allowed) ----
__device__ int g_row_ptr[N_NODES + 1];
// x quantized to fp16: 50000*128 halves = 12.8 MB, stored as uint4 (8 halves each)
__device__ uint4 g_x_half[(size_t)N_NODES * D_FEAT / 8];

// ---- prologue 1: convert x (f32) -> fp16 packed, 2 uint4 per thread ----
__global__ __launch_bounds__(256)
void convert_x_kernel(const float* __restrict__ x) {
    const int total = N_NODES * D_FEAT / 8;         // uint4 outputs
    int i = (blockIdx.x * blockDim.x + threadIdx.x) * 2;
    const float4* __restrict__ x4 = (const float4*)x;

    #pragma unroll
    for (int k = 0; k < 2; k++) {
        int o = i + k;
        if (o >= total) break;
        float4 a = x4[o * 2 + 0];
        float4 b = x4[o * 2 + 1];
        __half2 h0 = __floats2half2_rn(a.x, a.y);
        __half2 h1 = __floats2half2_rn(a.z, a.w);
        __half2 h2 = __floats2half2_rn(b.x, b.y);
        __half2 h3 = __floats2half2_rn(b.z, b.w);
        uint4 outv;
        outv.x = *(unsigned int*)&h0;
        outv.y = *(unsigned int*)&h1;
        outv.z = *(unsigned int*)&h2;
        outv.w = *(unsigned int*)&h3;
        g_x_half[o] = outv;
    }
}

// ---- prologue 2: CSR row_ptr from sorted COO rows (edge-parallel) ----
__global__ void build_row_ptr_kernel(const int* __restrict__ rows) {
    int e = blockIdx.x * blockDim.x + threadIdx.x;
    if (e >= N_EDGES) return;
    int r = rows[e];
    int rprev = (e == 0) ? -1 : rows[e - 1];
    for (int q = rprev + 1; q <= r; q++) g_row_ptr[q] = e;
    if (e == N_EDGES - 1) {
        for (int q = r + 1; q <= N_NODES; q++) g_row_ptr[q] = N_EDGES;
    }
}

// ---- main: one warp per row, paired-edge fp16 gather, fp32 accumulate ----
// Lanes 0-15 serve even edges, lanes 16-31 odd edges. Each lane loads one
// uint4 (8 halves) per edge-pair step -> one LDG.128 warp instruction moves
// 512 B covering TWO edges. Epilogue folds the two halves via shfl_xor(16).
__global__ __launch_bounds__(256)
void spmm_coo_kernel(const float* __restrict__ vals,
                     const int* __restrict__ cols,
                     float* __restrict__ out) {
    int warp = (blockIdx.x * blockDim.x + threadIdx.x) >> 5;
    int lane = threadIdx.x & 31;
    if (warp >= N_NODES) return;

    int start = g_row_ptr[warp];
    int end   = g_row_ptr[warp + 1];

    int half = lane >> 4;        // 0: even edges, 1: odd edges
    int sub  = lane & 15;        // feature sub-slot: halves [8*sub, 8*sub+8)

    float acc[8];
    #pragma unroll
    for (int k = 0; k < 8; k++) acc[k] = 0.f;

    for (int base = start; base < end; base += 32) {
        int n = end - base;
        if (n > 32) n = 32;

        // Cooperative, coalesced load of this chunk's edge metadata.
        // Lanes >= n hold c=0, v=0 so overshoot shuffles contribute nothing.
        int   c = 0;
        float v = 0.f;
        if (lane < n) {
            c = cols[base + lane];
            v = vals[base + lane];
        }

        #pragma unroll 4
        for (int j = 0; j < n; j += 2) {
            int e = j + half;                         // <= 31 always
            int   cj = __shfl_sync(0xffffffffu, c, e);
            float vj = __shfl_sync(0xffffffffu, v, e);
            uint4 h  = g_x_half[(size_t)cj * (D_FEAT / 8) + sub];
            float2 f0 = __half22float2(*(__half2*)&h.x);
            float2 f1 = __half22float2(*(__half2*)&h.y);
            float2 f2 = __half22float2(*(__half2*)&h.z);
            float2 f3 = __half22float2(*(__half2*)&h.w);
            acc[0] += vj * f0.x;  acc[1] += vj * f0.y;
            acc[2] += vj * f1.x;  acc[3] += vj * f1.y;
            acc[4] += vj * f2.x;  acc[5] += vj * f2.y;
            acc[6] += vj * f3.x;  acc[7] += vj * f3.y;
        }
    }

    // Fold even/odd edge partials: lanes l and l^16 hold the same features.
    #pragma unroll
    for (int k = 0; k < 8; k++)
        acc[k] += __shfl_xor_sync(0xffffffffu, acc[k], 16);

    // Each lane stores one float4: half 0 -> low quad, half 1 -> high quad.
    float4 st;
    if (half == 0) st = make_float4(acc[0], acc[1], acc[2], acc[3]);
    else           st = make_float4(acc[4], acc[5], acc[6], acc[7]);
    ((float4*)out)[(size_t)warp * (D_FEAT / 4) + 2 * sub + half] = st;
}

extern "C" void kernel_launch(void* const* d_in, const int* in_sizes, int n_in,
                              void* d_out, int out_size) {
    const float* x    = (const float*)d_in[0];
    const float* vals = (const float*)d_in[1];
    const int*   rows = (const int*)d_in[2];
    const int*   cols = (const int*)d_in[3];
    float*       out  = (float*)d_out;

    (void)in_sizes; (void)n_in; (void)out_size;

    // 1) x -> fp16 (halves gather traffic through L2)
    {
        int total_u4 = N_NODES * D_FEAT / 8;         // 800k uint4
        int threads  = 256;
        int blocks   = (total_u4 / 2 + threads - 1) / threads;
        convert_x_kernel<<<blocks, threads>>>(x);
    }

    // 2) CSR row_ptr from sorted COO rows
    {
        int threads = 256;
        int blocks  = (N_EDGES + threads - 1) / threads;
        build_row_ptr_kernel<<<blocks, threads>>>(rows);
    }

    // 3) Warp-per-row SpMM, paired-edge fp16 gather, fp32 accumulate
    {
        int threads = 256;  // 8 warps/block
        int blocks  = (N_NODES * 32 + threads - 1) / threads;
        spmm_coo_kernel<<<blocks, threads>>>(vals, cols, out);
    }
}

// round 4
// speedup vs baseline: 1.2247x; 1.2247x over previous
#include <cuda_runtime.h>
#include <cuda_fp16.h>

#define N_NODES 50000
#define N_EDGES 800000
#define D_FEAT  128

// ---- device-global scratch (no runtime allocation allowed) ----
__device__ int g_row_ptr[N_NODES + 1];
// x quantized to fp16: 50000*128 halves = 12.8 MB, stored as uint4 (8 halves)
__device__ uint4 g_x_half[(size_t)N_NODES * D_FEAT / 8];   // exactly N_EDGES entries
// vals as replicated half2 (bit pattern in uint)
__device__ unsigned int g_vh[N_EDGES];

// ---- fused prologue: one thread per edge does 3 small jobs ----
// (N_NODES*D_FEAT/8 == N_EDGES == 800000, so one grid covers all three.)
__global__ __launch_bounds__(256)
void prologue_kernel(const float* __restrict__ x,
                     const float* __restrict__ vals,
                     const int* __restrict__ rows) {
    int t = blockIdx.x * blockDim.x + threadIdx.x;
    if (t >= N_EDGES) return;

    // 1) x -> fp16: t-th uint4 covers floats [8t, 8t+8)
    {
        const float4* __restrict__ x4 = (const float4*)x;
        float4 a = x4[2 * t + 0];
        float4 b = x4[2 * t + 1];
        __half2 h0 = __floats2half2_rn(a.x, a.y);
        __half2 h1 = __floats2half2_rn(a.z, a.w);
        __half2 h2 = __floats2half2_rn(b.x, b.y);
        __half2 h3 = __floats2half2_rn(b.z, b.w);
        uint4 o;
        o.x = *(unsigned int*)&h0; o.y = *(unsigned int*)&h1;
        o.z = *(unsigned int*)&h2; o.w = *(unsigned int*)&h3;
        g_x_half[t] = o;
    }

    // 2) vals -> replicated half2
    {
        __half  hv = __float2half_rn(vals[t]);
        __half2 v2 = __half2half2(hv);
        g_vh[t] = *(unsigned int*)&v2;
    }

    // 3) CSR row_ptr from sorted COO rows
    {
        int r = rows[t];
        int rprev = (t == 0) ? -1 : rows[t - 1];
        for (int q = rprev + 1; q <= r; q++) g_row_ptr[q] = t;
        if (t == N_EDGES - 1) {
            for (int q = r + 1; q <= N_NODES; q++) g_row_ptr[q] = N_EDGES;
        }
    }
}

// ---- main: warp per row, paired-edge fp16 gather, HFMA2, fp32 flush ----
// Lanes 0-15 serve even edges, 16-31 odd edges. Each lane loads one uint4
// (8 halves) per step; accumulates in half2 for at most 8 edges (4 steps),
// then flushes into fp32 accumulators. Atomic-free (rows sorted).
__global__ __launch_bounds__(256)
void spmm_coo_kernel(const int* __restrict__ cols,
                     float* __restrict__ out) {
    int warp = (blockIdx.x * blockDim.x + threadIdx.x) >> 5;
    int lane = threadIdx.x & 31;
    if (warp >= N_NODES) return;

    int start = g_row_ptr[warp];
    int end   = g_row_ptr[warp + 1];

    int half = lane >> 4;        // 0: even edges, 1: odd edges
    int sub  = lane & 15;        // owns halves [8*sub, 8*sub+8)

    float acc[8];
    #pragma unroll
    for (int k = 0; k < 8; k++) acc[k] = 0.f;

    for (int base = start; base < end; base += 32) {
        int n = end - base;
        if (n > 32) n = 32;

        // Cooperative coalesced load of chunk metadata; masked lanes are
        // exact zeros (c=0 -> harmless x[0] gather, vh=0 -> contributes 0).
        int          c  = 0;
        unsigned int vh = 0;
        if (lane < n) {
            c  = cols[base + lane];
            vh = g_vh[base + lane];
        }

        int nsub = (n + 7) >> 3;              // 1..4 sub-blocks of 8 edges
        for (int b = 0; b < nsub; b++) {
            __half2 a0 = __half2half2(__ushort_as_half(0));
            __half2 a1 = a0, a2 = a0, a3 = a0;

            #pragma unroll
            for (int s = 0; s < 4; s++) {
                int j = b * 8 + s * 2 + half;           // <= 31 always
                int          cj = __shfl_sync(0xffffffffu, c,  j);
                unsigned int vj = __shfl_sync(0xffffffffu, vh, j);
                __half2 v2 = *(__half2*)&vj;
                uint4 h = g_x_half[(size_t)cj * (D_FEAT / 8) + sub];
                a0 = __hfma2(*(__half2*)&h.x, v2, a0);
                a1 = __hfma2(*(__half2*)&h.y, v2, a1);
                a2 = __hfma2(*(__half2*)&h.z, v2, a2);
                a3 = __hfma2(*(__half2*)&h.w, v2, a3);
            }

            // Flush half2 partials into fp32 accumulators.
            float2 f0 = __half22float2(a0);
            float2 f1 = __half22float2(a1);
            float2 f2 = __half22float2(a2);
            float2 f3 = __half22float2(a3);
            acc[0] += f0.x; acc[1] += f0.y;
            acc[2] += f1.x; acc[3] += f1.y;
            acc[4] += f2.x; acc[5] += f2.y;
            acc[6] += f3.x; acc[7] += f3.y;
        }
    }

    // Fold even/odd edge partials: lanes l and l^16 hold the same features.
    #pragma unroll
    for (int k = 0; k < 8; k++)
        acc[k] += __shfl_xor_sync(0xffffffffu, acc[k], 16);

    // Each lane stores one float4: half 0 -> low quad, half 1 -> high quad.
    float4 st;
    if (half == 0) st = make_float4(acc[0], acc[1], acc[2], acc[3]);
    else           st = make_float4(acc[4], acc[5], acc[6], acc[7]);
    ((float4*)out)[(size_t)warp * (D_FEAT / 4) + 2 * sub + half] = st;
}

extern "C" void kernel_launch(void* const* d_in, const int* in_sizes, int n_in,
                              void* d_out, int out_size) {
    const float* x    = (const float*)d_in[0];
    const float* vals = (const float*)d_in[1];
    const int*   rows = (const int*)d_in[2];
    const int*   cols = (const int*)d_in[3];
    float*       out  = (float*)d_out;

    (void)in_sizes; (void)n_in; (void)out_size;

    // 1) Fused prologue: x->fp16, vals->half2, row_ptr
    {
        int threads = 256;
        int blocks  = (N_EDGES + threads - 1) / threads;
        prologue_kernel<<<blocks, threads>>>(x, vals, rows);
    }

    // 2) Warp-per-row SpMM
    {
        int threads = 256;  // 8 warps/block
        int blocks  = (N_NODES * 32 + threads - 1) / threads;
        spmm_coo_kernel<<<blocks, threads>>>(cols, out);
    }
}